// round 1
// baseline (speedup 1.0000x reference)
#include <cuda_runtime.h>
#include <math.h>

// Problem constants
#define BSZ 4
#define SEQ 2048
#define DM  1024
#define NH  16
#define DH  64
#define NROWS (BSZ * SEQ)        // 8192
#define SCALE_F 0.125f           // 1/sqrt(64)

// ---------------------------------------------------------------------------
// Device scratch (static globals — no runtime allocation, per harness rules)
// ---------------------------------------------------------------------------
static __device__ float g_q[(size_t)NROWS * DM];
static __device__ float g_k[(size_t)NROWS * DM];
static __device__ float g_v[(size_t)NROWS * DM];
static __device__ float g_att[(size_t)NROWS * DM];

// ---------------------------------------------------------------------------
// SGEMM: C = A[M,K] @ B[K,N] + bias, 128x128x16 tiles, 256 threads, 8x8/thread
// grid.z selects among up to 3 (B, bias, C) triples (fused QKV projection).
// ---------------------------------------------------------------------------
__global__ __launch_bounds__(256) void sgemm3_kernel(
    const float* __restrict__ A,
    const float* __restrict__ B0, const float* __restrict__ B1, const float* __restrict__ B2,
    const float* __restrict__ bias0, const float* __restrict__ bias1, const float* __restrict__ bias2,
    float* __restrict__ C0, float* __restrict__ C1, float* __restrict__ C2,
    int M, int N, int K)
{
    const float* B;
    const float* bias;
    float* C;
    if (blockIdx.z == 0)      { B = B0; bias = bias0; C = C0; }
    else if (blockIdx.z == 1) { B = B1; bias = bias1; C = C1; }
    else                      { B = B2; bias = bias2; C = C2; }

    __shared__ float As[16][132];   // A tile transposed: As[k][m], pitch 132
    __shared__ float Bs[16][132];   // B tile: Bs[k][n], pitch 132

    const int tid = threadIdx.x;
    const int tx = tid & 15;
    const int ty = tid >> 4;
    const int m0 = blockIdx.y * 128;
    const int n0 = blockIdx.x * 128;

    float acc[8][8];
#pragma unroll
    for (int i = 0; i < 8; i++)
#pragma unroll
        for (int j = 0; j < 8; j++) acc[i][j] = 0.f;

    for (int kk = 0; kk < K; kk += 16) {
        // Load A tile 128x16 (transposed into As[k][m])
#pragma unroll
        for (int t = 0; t < 2; t++) {
            int f = tid + t * 256;            // 0..511  (512 float4s)
            int row = f >> 2;                 // 0..127
            int kq = (f & 3) << 2;            // 0,4,8,12
            float4 v = *(const float4*)(A + (size_t)(m0 + row) * K + kk + kq);
            As[kq + 0][row] = v.x;
            As[kq + 1][row] = v.y;
            As[kq + 2][row] = v.z;
            As[kq + 3][row] = v.w;
        }
        // Load B tile 16x128
#pragma unroll
        for (int t = 0; t < 2; t++) {
            int f = tid + t * 256;
            int row = f >> 5;                 // 0..15
            int c = (f & 31) << 2;            // 0..124
            *(float4*)(&Bs[row][c]) = *(const float4*)(B + (size_t)(kk + row) * N + n0 + c);
        }
        __syncthreads();

#pragma unroll
        for (int k = 0; k < 16; k++) {
            float4 a0  = *(const float4*)(&As[k][ty * 4]);
            float4 a1  = *(const float4*)(&As[k][64 + ty * 4]);
            float4 bv0 = *(const float4*)(&Bs[k][tx * 4]);
            float4 bv1 = *(const float4*)(&Bs[k][64 + tx * 4]);
            float a[8]  = {a0.x, a0.y, a0.z, a0.w, a1.x, a1.y, a1.z, a1.w};
            float bb[8] = {bv0.x, bv0.y, bv0.z, bv0.w, bv1.x, bv1.y, bv1.z, bv1.w};
#pragma unroll
            for (int i = 0; i < 8; i++)
#pragma unroll
                for (int j = 0; j < 8; j++)
                    acc[i][j] += a[i] * bb[j];
        }
        __syncthreads();
    }

    // Epilogue: add bias, store float4
#pragma unroll
    for (int i = 0; i < 8; i++) {
        int row = m0 + ((i < 4) ? (ty * 4 + i) : (64 + ty * 4 + i - 4));
#pragma unroll
        for (int jh = 0; jh < 2; jh++) {
            int col = n0 + jh * 64 + tx * 4;
            float4 r;
            r.x = acc[i][jh * 4 + 0] + bias[col + 0];
            r.y = acc[i][jh * 4 + 1] + bias[col + 1];
            r.z = acc[i][jh * 4 + 2] + bias[col + 2];
            r.w = acc[i][jh * 4 + 3] + bias[col + 3];
            *(float4*)(C + (size_t)row * N + col) = r;
        }
    }
}

// ---------------------------------------------------------------------------
// Flash attention: per (b, h, 64-query tile). Online softmax over 64-key tiles.
// 256 threads; S-stage: rows ty+16i, cols tx+16j (4x4); PV-stage O cols tx*4+j.
// smem pitch 68 floats => consecutive-lane float4 addresses stride 16B mod 128
// => conflict-free LDS.128.
// ---------------------------------------------------------------------------
#define PITCH 68
#define FLASH_SMEM (4 * 64 * PITCH * 4 + 64 * 4)

__global__ __launch_bounds__(256) void flash_kernel(
    const float* __restrict__ Q, const float* __restrict__ K,
    const float* __restrict__ V, const int* __restrict__ mask,
    float* __restrict__ O)
{
    extern __shared__ float sm[];
    float* Qs = sm;
    float* Ks = Qs + 64 * PITCH;
    float* Vs = Ks + 64 * PITCH;
    float* Ps = Vs + 64 * PITCH;
    int*   msk = (int*)(Ps + 64 * PITCH);

    const int b = blockIdx.z;
    const int h = blockIdx.y;
    const int q0 = blockIdx.x * 64;
    const int tid = threadIdx.x;
    const int tx = tid & 15;
    const int ty = tid >> 4;

    // Load Q tile (64 rows x 64 head-dim)
    const float* Qg = Q + ((size_t)(b * SEQ + q0) * DM + h * DH);
#pragma unroll
    for (int t = 0; t < 4; t++) {
        int f = tid + t * 256;
        int row = f >> 4, c4 = f & 15;
        *(float4*)(Qs + row * PITCH + c4 * 4) =
            *(const float4*)(Qg + (size_t)row * DM + c4 * 4);
    }

    float acc[4][4];
    float mrow[4], lrow[4];
#pragma unroll
    for (int i = 0; i < 4; i++) {
        mrow[i] = -INFINITY;
        lrow[i] = 0.f;
#pragma unroll
        for (int j = 0; j < 4; j++) acc[i][j] = 0.f;
    }

    for (int kt = 0; kt < SEQ / 64; kt++) {
        __syncthreads();   // previous PV done before overwriting Ks/Vs
        const float* Kg = K + ((size_t)(b * SEQ + kt * 64) * DM + h * DH);
        const float* Vg = V + ((size_t)(b * SEQ + kt * 64) * DM + h * DH);
#pragma unroll
        for (int t = 0; t < 4; t++) {
            int f = tid + t * 256;
            int row = f >> 4, c4 = f & 15;
            *(float4*)(Ks + row * PITCH + c4 * 4) = *(const float4*)(Kg + (size_t)row * DM + c4 * 4);
            *(float4*)(Vs + row * PITCH + c4 * 4) = *(const float4*)(Vg + (size_t)row * DM + c4 * 4);
        }
        if (tid < 64) msk[tid] = mask[b * SEQ + kt * 64 + tid];
        __syncthreads();

        // ---- S = Q K^T (4x4 per thread, float4 over k) ----
        float s[4][4];
#pragma unroll
        for (int i = 0; i < 4; i++)
#pragma unroll
            for (int j = 0; j < 4; j++) s[i][j] = 0.f;

#pragma unroll
        for (int k4 = 0; k4 < 16; k4++) {
            float4 qv[4], kv[4];
#pragma unroll
            for (int i = 0; i < 4; i++)
                qv[i] = *(const float4*)(Qs + (ty + 16 * i) * PITCH + k4 * 4);
#pragma unroll
            for (int j = 0; j < 4; j++)
                kv[j] = *(const float4*)(Ks + (tx + 16 * j) * PITCH + k4 * 4);
#pragma unroll
            for (int i = 0; i < 4; i++)
#pragma unroll
                for (int j = 0; j < 4; j++)
                    s[i][j] += qv[i].x * kv[j].x + qv[i].y * kv[j].y +
                               qv[i].z * kv[j].z + qv[i].w * kv[j].w;
        }

        // ---- scale + key-padding mask (mask==1 -> exactly -1e30, as reference) ----
        int mloc[4];
#pragma unroll
        for (int j = 0; j < 4; j++) mloc[j] = msk[tx + 16 * j];
#pragma unroll
        for (int i = 0; i < 4; i++)
#pragma unroll
            for (int j = 0; j < 4; j++)
                s[i][j] = mloc[j] ? -1e30f : s[i][j] * SCALE_F;

        // ---- online softmax per row (16 lanes share a row; xor-shuffle reduce) ----
#pragma unroll
        for (int i = 0; i < 4; i++) {
            float mx = fmaxf(fmaxf(s[i][0], s[i][1]), fmaxf(s[i][2], s[i][3]));
#pragma unroll
            for (int off = 1; off < 16; off <<= 1)
                mx = fmaxf(mx, __shfl_xor_sync(0xffffffffu, mx, off));
            float mnew = fmaxf(mrow[i], mx);
            float rs = 0.f;
#pragma unroll
            for (int j = 0; j < 4; j++) {
                float p = __expf(s[i][j] - mnew);
                Ps[(ty + 16 * i) * PITCH + tx + 16 * j] = p;
                rs += p;
            }
#pragma unroll
            for (int off = 1; off < 16; off <<= 1)
                rs += __shfl_xor_sync(0xffffffffu, rs, off);
            float alpha = __expf(mrow[i] - mnew);
            lrow[i] = lrow[i] * alpha + rs;
            mrow[i] = mnew;
#pragma unroll
            for (int j = 0; j < 4; j++) acc[i][j] *= alpha;
        }
        __syncthreads();   // P visible to all lanes

        // ---- O += P V  (O cols d = tx*4+j, float4 over keys) ----
#pragma unroll
        for (int c4 = 0; c4 < 16; c4++) {
            float4 pv[4], vv[4];
#pragma unroll
            for (int i = 0; i < 4; i++)
                pv[i] = *(const float4*)(Ps + (ty + 16 * i) * PITCH + c4 * 4);
#pragma unroll
            for (int t = 0; t < 4; t++)
                vv[t] = *(const float4*)(Vs + (c4 * 4 + t) * PITCH + tx * 4);
#pragma unroll
            for (int i = 0; i < 4; i++) {
                float p0 = pv[i].x, p1 = pv[i].y, p2 = pv[i].z, p3 = pv[i].w;
                acc[i][0] += p0 * vv[0].x + p1 * vv[1].x + p2 * vv[2].x + p3 * vv[3].x;
                acc[i][1] += p0 * vv[0].y + p1 * vv[1].y + p2 * vv[2].y + p3 * vv[3].y;
                acc[i][2] += p0 * vv[0].z + p1 * vv[1].z + p2 * vv[2].z + p3 * vv[3].z;
                acc[i][3] += p0 * vv[0].w + p1 * vv[1].w + p2 * vv[2].w + p3 * vv[3].w;
            }
        }
    }

    // ---- epilogue: normalize, store [b, q, h*64 + d] ----
#pragma unroll
    for (int i = 0; i < 4; i++) {
        float inv = 1.f / lrow[i];
        int row = q0 + ty + 16 * i;
        float4 r;
        r.x = acc[i][0] * inv;
        r.y = acc[i][1] * inv;
        r.z = acc[i][2] * inv;
        r.w = acc[i][3] * inv;
        *(float4*)(O + ((size_t)(b * SEQ + row) * DM + h * DH + tx * 4)) = r;
    }
}

// ---------------------------------------------------------------------------
// kernel_launch: QKV projections -> flash attention -> output projection
// ---------------------------------------------------------------------------
extern "C" void kernel_launch(void* const* d_in, const int* in_sizes, int n_in,
                              void* d_out, int out_size)
{
    const float* x    = (const float*)d_in[0];
    const int*   mask = (const int*)  d_in[1];
    const float* Wq   = (const float*)d_in[2];
    const float* bq   = (const float*)d_in[3];
    const float* Wk   = (const float*)d_in[4];
    const float* bk   = (const float*)d_in[5];
    const float* Wv   = (const float*)d_in[6];
    const float* bv   = (const float*)d_in[7];
    const float* Wf   = (const float*)d_in[8];
    const float* bf   = (const float*)d_in[9];
    float* out = (float*)d_out;

    float *q, *k, *v, *att;
    cudaGetSymbolAddress((void**)&q,   g_q);
    cudaGetSymbolAddress((void**)&k,   g_k);
    cudaGetSymbolAddress((void**)&v,   g_v);
    cudaGetSymbolAddress((void**)&att, g_att);

    dim3 blk(256);

    // 1) fused Q/K/V projections
    dim3 g1(DM / 128, NROWS / 128, 3);
    sgemm3_kernel<<<g1, blk>>>(x, Wq, Wk, Wv, bq, bk, bv, q, k, v, NROWS, DM, DM);

    // 2) flash attention
    cudaFuncSetAttribute(flash_kernel, cudaFuncAttributeMaxDynamicSharedMemorySize, FLASH_SMEM);
    dim3 g2(SEQ / 64, NH, BSZ);
    flash_kernel<<<g2, blk, FLASH_SMEM>>>(q, k, v, mask, att);

    // 3) output projection
    dim3 g3(DM / 128, NROWS / 128, 1);
    sgemm3_kernel<<<g3, blk>>>(att, Wf, Wf, Wf, bf, bf, bf, out, out, out, NROWS, DM, DM);
}

// round 2
// speedup vs baseline: 2.5431x; 2.5431x over previous
#include <cuda_runtime.h>
#include <math.h>
#include <stdint.h>

// Problem constants
#define BSZ 4
#define SEQ 2048
#define DM  1024
#define NH  16
#define DH  64
#define NROWS (BSZ * SEQ)        // 8192
#define SCALE_F 0.125f           // 1/sqrt(64)

// ---------------------------------------------------------------------------
// Device scratch (static globals — no runtime allocation, per harness rules)
// ---------------------------------------------------------------------------
static __device__ float g_q[(size_t)NROWS * DM];
static __device__ float g_k[(size_t)NROWS * DM];
static __device__ float g_v[(size_t)NROWS * DM];
static __device__ float g_att[(size_t)NROWS * DM];

// ---------------------------------------------------------------------------
// Helpers: TF32 round (RNA) + m16n8k8 TF32 tensor-core MMA
// ---------------------------------------------------------------------------
__device__ __forceinline__ float tf32r(float x) {
    uint32_t u;
    asm("cvt.rna.tf32.f32 %0, %1;" : "=r"(u) : "f"(x));
    return __uint_as_float(u);
}
__device__ __forceinline__ float4 tf32r4(float4 v) {
    return make_float4(tf32r(v.x), tf32r(v.y), tf32r(v.z), tf32r(v.w));
}
__device__ __forceinline__ uint32_t fbits(float x) { return __float_as_uint(x); }

// D(16x8,f32) += A(16x8 tf32, row) * B(8x8 tf32, col)
__device__ __forceinline__ void mma8(float* d, const uint32_t* a, const uint32_t* b) {
    asm volatile(
        "mma.sync.aligned.m16n8k8.row.col.f32.tf32.tf32.f32 "
        "{%0,%1,%2,%3},{%4,%5,%6,%7},{%8,%9},{%0,%1,%2,%3};\n"
        : "+f"(d[0]), "+f"(d[1]), "+f"(d[2]), "+f"(d[3])
        : "r"(a[0]), "r"(a[1]), "r"(a[2]), "r"(a[3]), "r"(b[0]), "r"(b[1]));
}

// ---------------------------------------------------------------------------
// TF32 GEMM: C = A[M,K]@B[K,N] + bias.  Block 128x128, K-tile 32, 256 thr.
// Warp grid 4(m) x 2(n); warp tile 32x64 = 2 m-tiles x 8 n-tiles of m16n8k8.
// Smem pitches (A:36, B:136) chosen so fragment LDS hits 32 distinct banks.
// grid.z selects among up to 3 (B, bias, C) triples (fused QKV projection).
// ---------------------------------------------------------------------------
__global__ __launch_bounds__(256) void gemm_tf32_kernel(
    const float* __restrict__ A,
    const float* __restrict__ B0, const float* __restrict__ B1, const float* __restrict__ B2,
    const float* __restrict__ bias0, const float* __restrict__ bias1, const float* __restrict__ bias2,
    float* __restrict__ C0, float* __restrict__ C1, float* __restrict__ C2)
{
    const float* B; const float* bias; float* C;
    if (blockIdx.z == 0)      { B = B0; bias = bias0; C = C0; }
    else if (blockIdx.z == 1) { B = B1; bias = bias1; C = C1; }
    else                      { B = B2; bias = bias2; C = C2; }

    __shared__ float As[128][36];   // [m][k], pitch 36: (4m+k)%32 distinct over frag quads
    __shared__ float Bs[32][136];   // [k][n], pitch 136: (8k+n)%32 distinct over frag quads

    const int tid = threadIdx.x;
    const int lane = tid & 31;
    const int w    = tid >> 5;
    const int wm   = w & 3;          // warp m index (0..3)
    const int wn   = w >> 2;         // warp n index (0..1)
    const int grp  = lane >> 2;      // 0..7
    const int t4   = lane & 3;       // 0..3
    const int m0 = blockIdx.y * 128;
    const int n0 = blockIdx.x * 128;

    float acc[2][8][4];
#pragma unroll
    for (int mt = 0; mt < 2; mt++)
#pragma unroll
        for (int nt = 0; nt < 8; nt++)
#pragma unroll
            for (int c = 0; c < 4; c++) acc[mt][nt][c] = 0.f;

    for (int kk = 0; kk < DM; kk += 32) {
        // A tile 128x32 (1024 float4), round to tf32
#pragma unroll
        for (int t = 0; t < 4; t++) {
            int f = tid + t * 256;
            int r = f >> 3, c = (f & 7) * 4;
            float4 v = *(const float4*)(A + (size_t)(m0 + r) * DM + kk + c);
            *(float4*)&As[r][c] = tf32r4(v);
        }
        // B tile 32x128 (1024 float4), round to tf32
#pragma unroll
        for (int t = 0; t < 4; t++) {
            int f = tid + t * 256;
            int r = f >> 5, c = (f & 31) * 4;
            float4 v = *(const float4*)(B + (size_t)(kk + r) * DM + n0 + c);
            *(float4*)&Bs[r][c] = tf32r4(v);
        }
        __syncthreads();

#pragma unroll
        for (int k8 = 0; k8 < 4; k8++) {
            const int kb = k8 * 8;
            uint32_t af[2][4], bf[8][2];
#pragma unroll
            for (int mt = 0; mt < 2; mt++) {
                int r = wm * 32 + mt * 16 + grp;
                af[mt][0] = fbits(As[r][kb + t4]);
                af[mt][1] = fbits(As[r + 8][kb + t4]);
                af[mt][2] = fbits(As[r][kb + t4 + 4]);
                af[mt][3] = fbits(As[r + 8][kb + t4 + 4]);
            }
#pragma unroll
            for (int nt = 0; nt < 8; nt++) {
                int n = wn * 64 + nt * 8 + grp;
                bf[nt][0] = fbits(Bs[kb + t4][n]);
                bf[nt][1] = fbits(Bs[kb + t4 + 4][n]);
            }
#pragma unroll
            for (int mt = 0; mt < 2; mt++)
#pragma unroll
                for (int nt = 0; nt < 8; nt++)
                    mma8(acc[mt][nt], af[mt], bf[nt]);
        }
        __syncthreads();
    }

    // Epilogue: bias add, float2 stores (c0,c1 are adjacent columns)
#pragma unroll
    for (int mt = 0; mt < 2; mt++) {
        int r0 = m0 + wm * 32 + mt * 16 + grp;
#pragma unroll
        for (int nt = 0; nt < 8; nt++) {
            int col = n0 + wn * 64 + nt * 8 + t4 * 2;
            float b0v = bias[col], b1v = bias[col + 1];
            float2 v0 = make_float2(acc[mt][nt][0] + b0v, acc[mt][nt][1] + b1v);
            float2 v1 = make_float2(acc[mt][nt][2] + b0v, acc[mt][nt][3] + b1v);
            *(float2*)(C + (size_t)r0 * DM + col) = v0;
            *(float2*)(C + (size_t)(r0 + 8) * DM + col) = v1;
        }
    }
}

// ---------------------------------------------------------------------------
// Flash attention, TF32 tensor-core. Per CTA: (b, h, 64-query tile).
// 8 warps: qw = w&3 (16-query group), kw = w>>2 (key-half for S, d-half for PV).
// Online softmax with cross-warp (kw) max/sum reduction via smem.
// Smem pitches: Q/K/P = 68, V = 72  => all fragment LDS conflict-free.
// ---------------------------------------------------------------------------
#define QP 68
#define KP 68
#define VP 72
#define PP 68
#define FLASH_SMEM ((64 * (QP + KP + VP + PP) + 2 * 64 + 2 * 64 + 64) * 4)

__global__ __launch_bounds__(256) void flash_tf32_kernel(
    const float* __restrict__ Q, const float* __restrict__ K,
    const float* __restrict__ V, const int* __restrict__ mask,
    float* __restrict__ O)
{
    extern __shared__ float sm[];
    float* Qs  = sm;                  // [64][QP]
    float* Ks  = Qs + 64 * QP;        // [64][KP]
    float* Vs  = Ks + 64 * KP;        // [64][VP]
    float* Ps  = Vs + 64 * VP;        // [64][PP]
    float* redm = Ps + 64 * PP;       // [2][64]
    float* redl = redm + 128;         // [2][64]
    int*   mskp = (int*)(redl + 128); // [64]

    const int b  = blockIdx.z;
    const int h  = blockIdx.y;
    const int q0 = blockIdx.x * 64;
    const int tid  = threadIdx.x;
    const int lane = tid & 31;
    const int w    = tid >> 5;
    const int qw   = w & 3;
    const int kw   = w >> 2;
    const int grp  = lane >> 2;
    const int t4   = lane & 3;
    const int qrow = qw * 16 + grp;   // first of the 2 rows this thread owns

    // Load Q tile (rounded to tf32)
    const float* Qg = Q + ((size_t)(b * SEQ + q0) * DM + h * DH);
#pragma unroll
    for (int t = 0; t < 4; t++) {
        int f = tid + t * 256;
        int r = f >> 4, c = (f & 15) * 4;
        *(float4*)&Qs[r * QP + c] = tf32r4(*(const float4*)(Qg + (size_t)r * DM + c));
    }

    float o[4][4];
#pragma unroll
    for (int nt = 0; nt < 4; nt++)
#pragma unroll
        for (int c = 0; c < 4; c++) o[nt][c] = 0.f;
    float m0r = -INFINITY, m1r = -INFINITY, l0 = 0.f, l1 = 0.f;

    for (int kt = 0; kt < SEQ / 64; kt++) {
        __syncthreads();   // prior PV reads done before overwrite
        const float* Kg = K + ((size_t)(b * SEQ + kt * 64) * DM + h * DH);
        const float* Vg = V + ((size_t)(b * SEQ + kt * 64) * DM + h * DH);
#pragma unroll
        for (int t = 0; t < 4; t++) {
            int f = tid + t * 256;
            int r = f >> 4, c = (f & 15) * 4;
            *(float4*)&Ks[r * KP + c] = tf32r4(*(const float4*)(Kg + (size_t)r * DM + c));
            *(float4*)&Vs[r * VP + c] = tf32r4(*(const float4*)(Vg + (size_t)r * DM + c));
        }
        if (tid < 64) mskp[tid] = mask[b * SEQ + kt * 64 + tid];
        __syncthreads();

        // ---- S = Q K^T : warp computes S[16q x 32keys], keys offset kw*32 ----
        float s[4][4];
#pragma unroll
        for (int nt = 0; nt < 4; nt++)
#pragma unroll
            for (int c = 0; c < 4; c++) s[nt][c] = 0.f;

#pragma unroll
        for (int k8 = 0; k8 < 8; k8++) {
            const int kb = k8 * 8;
            uint32_t af[4];
            af[0] = fbits(Qs[qrow * QP + kb + t4]);
            af[1] = fbits(Qs[(qrow + 8) * QP + kb + t4]);
            af[2] = fbits(Qs[qrow * QP + kb + t4 + 4]);
            af[3] = fbits(Qs[(qrow + 8) * QP + kb + t4 + 4]);
#pragma unroll
            for (int nt = 0; nt < 4; nt++) {
                int key = kw * 32 + nt * 8 + grp;
                uint32_t bf[2] = { fbits(Ks[key * KP + kb + t4]),
                                   fbits(Ks[key * KP + kb + t4 + 4]) };
                mma8(s[nt], af, bf);
            }
        }

        // ---- scale + key-padding mask + per-thread row max ----
        float mx0 = -INFINITY, mx1 = -INFINITY;
#pragma unroll
        for (int nt = 0; nt < 4; nt++) {
            int key = kw * 32 + nt * 8 + t4 * 2;
            int mk0 = mskp[key], mk1 = mskp[key + 1];
            s[nt][0] = mk0 ? -1e30f : s[nt][0] * SCALE_F;
            s[nt][1] = mk1 ? -1e30f : s[nt][1] * SCALE_F;
            s[nt][2] = mk0 ? -1e30f : s[nt][2] * SCALE_F;
            s[nt][3] = mk1 ? -1e30f : s[nt][3] * SCALE_F;
            mx0 = fmaxf(mx0, fmaxf(s[nt][0], s[nt][1]));
            mx1 = fmaxf(mx1, fmaxf(s[nt][2], s[nt][3]));
        }
        // quad reduce (lanes of a group are consecutive: xor 1,2 stays in quad)
        mx0 = fmaxf(mx0, __shfl_xor_sync(0xffffffffu, mx0, 1));
        mx0 = fmaxf(mx0, __shfl_xor_sync(0xffffffffu, mx0, 2));
        mx1 = fmaxf(mx1, __shfl_xor_sync(0xffffffffu, mx1, 1));
        mx1 = fmaxf(mx1, __shfl_xor_sync(0xffffffffu, mx1, 2));
        if (t4 == 0) { redm[kw * 64 + qrow] = mx0; redm[kw * 64 + qrow + 8] = mx1; }
        __syncthreads();

        float mn0 = fmaxf(m0r, fmaxf(redm[qrow], redm[64 + qrow]));
        float mn1 = fmaxf(m1r, fmaxf(redm[qrow + 8], redm[64 + qrow + 8]));

        // ---- p = exp(s - mnew); store to Ps (tf32-rounded); partial row sums ----
        float ls0 = 0.f, ls1 = 0.f;
#pragma unroll
        for (int nt = 0; nt < 4; nt++) {
            float p0 = __expf(s[nt][0] - mn0), p1 = __expf(s[nt][1] - mn0);
            float p2 = __expf(s[nt][2] - mn1), p3 = __expf(s[nt][3] - mn1);
            ls0 += p0 + p1; ls1 += p2 + p3;
            int key = kw * 32 + nt * 8 + t4 * 2;
            *(float2*)&Ps[qrow * PP + key]       = make_float2(tf32r(p0), tf32r(p1));
            *(float2*)&Ps[(qrow + 8) * PP + key] = make_float2(tf32r(p2), tf32r(p3));
        }
        ls0 += __shfl_xor_sync(0xffffffffu, ls0, 1);
        ls0 += __shfl_xor_sync(0xffffffffu, ls0, 2);
        ls1 += __shfl_xor_sync(0xffffffffu, ls1, 1);
        ls1 += __shfl_xor_sync(0xffffffffu, ls1, 2);
        if (t4 == 0) { redl[kw * 64 + qrow] = ls0; redl[kw * 64 + qrow + 8] = ls1; }
        __syncthreads();   // Ps + redl complete

        float a0 = __expf(m0r - mn0), a1 = __expf(m1r - mn1);
        l0 = l0 * a0 + redl[qrow] + redl[64 + qrow];
        l1 = l1 * a1 + redl[qrow + 8] + redl[64 + qrow + 8];
        m0r = mn0; m1r = mn1;
#pragma unroll
        for (int nt = 0; nt < 4; nt++) {
            o[nt][0] *= a0; o[nt][1] *= a0; o[nt][2] *= a1; o[nt][3] *= a1;
        }

        // ---- O += P V : warp computes O[16q x 32d], d offset kw*32 ----
#pragma unroll
        for (int k8 = 0; k8 < 8; k8++) {
            const int kb = k8 * 8;
            uint32_t af[4];
            af[0] = fbits(Ps[qrow * PP + kb + t4]);
            af[1] = fbits(Ps[(qrow + 8) * PP + kb + t4]);
            af[2] = fbits(Ps[qrow * PP + kb + t4 + 4]);
            af[3] = fbits(Ps[(qrow + 8) * PP + kb + t4 + 4]);
#pragma unroll
            for (int nt = 0; nt < 4; nt++) {
                int d = kw * 32 + nt * 8 + grp;
                uint32_t bf[2] = { fbits(Vs[(kb + t4) * VP + d]),
                                   fbits(Vs[(kb + t4 + 4) * VP + d]) };
                mma8(o[nt], af, bf);
            }
        }
    }

    // ---- epilogue: normalize, store [b, q, h*64 + d] ----
    float inv0 = 1.f / l0, inv1 = 1.f / l1;
#pragma unroll
    for (int nt = 0; nt < 4; nt++) {
        int d = kw * 32 + nt * 8 + t4 * 2;
        float* Og = O + ((size_t)(b * SEQ + q0 + qrow) * DM + h * DH + d);
        *(float2*)Og = make_float2(o[nt][0] * inv0, o[nt][1] * inv0);
        *(float2*)(Og + (size_t)8 * DM) = make_float2(o[nt][2] * inv1, o[nt][3] * inv1);
    }
}

// ---------------------------------------------------------------------------
// kernel_launch: QKV projections -> flash attention -> output projection
// ---------------------------------------------------------------------------
extern "C" void kernel_launch(void* const* d_in, const int* in_sizes, int n_in,
                              void* d_out, int out_size)
{
    const float* x    = (const float*)d_in[0];
    const int*   mask = (const int*)  d_in[1];
    const float* Wq   = (const float*)d_in[2];
    const float* bq   = (const float*)d_in[3];
    const float* Wk   = (const float*)d_in[4];
    const float* bk   = (const float*)d_in[5];
    const float* Wv   = (const float*)d_in[6];
    const float* bv   = (const float*)d_in[7];
    const float* Wf   = (const float*)d_in[8];
    const float* bf   = (const float*)d_in[9];
    float* out = (float*)d_out;

    float *q, *k, *v, *att;
    cudaGetSymbolAddress((void**)&q,   g_q);
    cudaGetSymbolAddress((void**)&k,   g_k);
    cudaGetSymbolAddress((void**)&v,   g_v);
    cudaGetSymbolAddress((void**)&att, g_att);

    dim3 blk(256);

    // 1) fused Q/K/V projections (TF32 MMA)
    dim3 g1(DM / 128, NROWS / 128, 3);
    gemm_tf32_kernel<<<g1, blk>>>(x, Wq, Wk, Wv, bq, bk, bv, q, k, v);

    // 2) flash attention (TF32 MMA)
    static int smem_set = 0;
    if (!smem_set) {
        cudaFuncSetAttribute(flash_tf32_kernel,
                             cudaFuncAttributeMaxDynamicSharedMemorySize, FLASH_SMEM);
        smem_set = 1;
    }
    dim3 g2(SEQ / 64, NH, BSZ);
    flash_tf32_kernel<<<g2, blk, FLASH_SMEM>>>(q, k, v, mask, att);

    // 3) output projection (TF32 MMA)
    dim3 g3(DM / 128, NROWS / 128, 1);
    gemm_tf32_kernel<<<g3, blk>>>(att, Wf, Wf, Wf, bf, bf, bf, out, out, out);
}

// round 3
// speedup vs baseline: 3.0247x; 1.1894x over previous
#include <cuda_runtime.h>
#include <math.h>
#include <stdint.h>

// Problem constants
#define BSZ 4
#define SEQ 2048
#define DM  1024
#define NH  16
#define DH  64
#define NROWS (BSZ * SEQ)        // 8192
#define SCALE_F 0.125f           // 1/sqrt(64)

// ---------------------------------------------------------------------------
// Device scratch (static globals — no runtime allocation, per harness rules)
// ---------------------------------------------------------------------------
static __device__ float g_q[(size_t)NROWS * DM];
static __device__ float g_k[(size_t)NROWS * DM];
static __device__ float g_v[(size_t)NROWS * DM];
static __device__ float g_att[(size_t)NROWS * DM];

// ---------------------------------------------------------------------------
// Helpers
// ---------------------------------------------------------------------------
__device__ __forceinline__ float tf32r(float x) {
    uint32_t u;
    asm("cvt.rna.tf32.f32 %0, %1;" : "=r"(u) : "f"(x));
    return __uint_as_float(u);
}
__device__ __forceinline__ uint32_t tf32b(float x) {
    uint32_t u;
    asm("cvt.rna.tf32.f32 %0, %1;" : "=r"(u) : "f"(x));
    return u;
}
__device__ __forceinline__ float4 tf32r4(float4 v) {
    return make_float4(tf32r(v.x), tf32r(v.y), tf32r(v.z), tf32r(v.w));
}
__device__ __forceinline__ uint32_t fbits(float x) { return __float_as_uint(x); }

// D(16x8,f32) += A(16x8 tf32, row) * B(8x8 tf32, col)
__device__ __forceinline__ void mma8(float* d, const uint32_t* a, const uint32_t* b) {
    asm volatile(
        "mma.sync.aligned.m16n8k8.row.col.f32.tf32.tf32.f32 "
        "{%0,%1,%2,%3},{%4,%5,%6,%7},{%8,%9},{%0,%1,%2,%3};\n"
        : "+f"(d[0]), "+f"(d[1]), "+f"(d[2]), "+f"(d[3])
        : "r"(a[0]), "r"(a[1]), "r"(a[2]), "r"(a[3]), "r"(b[0]), "r"(b[1]));
}

__device__ __forceinline__ void cp16(float* dst_smem, const float* src) {
    uint32_t d = (uint32_t)__cvta_generic_to_shared(dst_smem);
    asm volatile("cp.async.cg.shared.global [%0], [%1], 16;\n" :: "r"(d), "l"(src));
}
#define CP_COMMIT() asm volatile("cp.async.commit_group;\n" ::: "memory")
#define CP_WAIT1()  asm volatile("cp.async.wait_group 1;\n" ::: "memory")

// ---------------------------------------------------------------------------
// TF32 GEMM, 3-stage cp.async pipeline.
// C = A[M,1024]@B[1024,N] + bias. Block 128x128, k-tile 16, 256 threads.
// Warp grid 4(m) x 2(n); warp tile 32x64. Raw fp32 staged in smem; cvt.rna at
// fragment load. Pitches A:20, B:136 -> conflict-free fragment LDS.
// grid.z selects among up to 3 (B, bias, C) triples (fused QKV projection).
// ---------------------------------------------------------------------------
#define GKT 16
#define A_ST (128 * 20)
#define B_ST (16 * 136)
#define STAGE_FLOATS (A_ST + B_ST)           // 4736 floats = 18944 B
#define GEMM_SMEM (3 * STAGE_FLOATS * 4)     // 56832 B

__global__ __launch_bounds__(256, 2) void gemm_tf32_kernel(
    const float* __restrict__ A,
    const float* __restrict__ B0, const float* __restrict__ B1, const float* __restrict__ B2,
    const float* __restrict__ bias0, const float* __restrict__ bias1, const float* __restrict__ bias2,
    float* __restrict__ C0, float* __restrict__ C1, float* __restrict__ C2)
{
    const float* B; const float* bias; float* C;
    if (blockIdx.z == 0)      { B = B0; bias = bias0; C = C0; }
    else if (blockIdx.z == 1) { B = B1; bias = bias1; C = C1; }
    else                      { B = B2; bias = bias2; C = C2; }

    extern __shared__ float smg[];

    const int tid = threadIdx.x;
    const int lane = tid & 31;
    const int w    = tid >> 5;
    const int wm   = w & 3;
    const int wn   = w >> 2;
    const int grp  = lane >> 2;
    const int t4   = lane & 3;
    const int m0 = blockIdx.y * 128;
    const int n0 = blockIdx.x * 128;

    // per-thread staged-load coordinates
    const int ar0 = tid >> 2,  ac = (tid & 3) * 4;   // A: rows ar0, ar0+64
    const int br0 = tid >> 5,  bc = (tid & 31) * 4;  // B: rows br0, br0+8

    auto issue = [&](int kk, int s) {
        float* As = smg + s * STAGE_FLOATS;
        float* Bs = As + A_ST;
        cp16(As + ar0 * 20 + ac,        A + (size_t)(m0 + ar0) * DM + kk + ac);
        cp16(As + (ar0 + 64) * 20 + ac, A + (size_t)(m0 + ar0 + 64) * DM + kk + ac);
        cp16(Bs + br0 * 136 + bc,       B + (size_t)(kk + br0) * DM + n0 + bc);
        cp16(Bs + (br0 + 8) * 136 + bc, B + (size_t)(kk + br0 + 8) * DM + n0 + bc);
    };

    float acc[2][8][4];
#pragma unroll
    for (int mt = 0; mt < 2; mt++)
#pragma unroll
        for (int nt = 0; nt < 8; nt++)
#pragma unroll
            for (int c = 0; c < 4; c++) acc[mt][nt][c] = 0.f;

    issue(0, 0);        CP_COMMIT();
    issue(GKT, 1);      CP_COMMIT();

    const int NKT = DM / GKT;   // 64
    for (int kt = 0; kt < NKT; kt++) {
        CP_WAIT1();
        __syncthreads();
        const int s = kt % 3;
        const float* As = smg + s * STAGE_FLOATS;
        const float* Bs = As + A_ST;

        if (kt + 2 < NKT) issue((kt + 2) * GKT, (kt + 2) % 3);
        CP_COMMIT();

#pragma unroll
        for (int k8 = 0; k8 < 2; k8++) {
            const int kb = k8 * 8;
            uint32_t af[2][4], bf[8][2];
#pragma unroll
            for (int mt = 0; mt < 2; mt++) {
                int r = wm * 32 + mt * 16 + grp;
                af[mt][0] = tf32b(As[r * 20 + kb + t4]);
                af[mt][1] = tf32b(As[(r + 8) * 20 + kb + t4]);
                af[mt][2] = tf32b(As[r * 20 + kb + t4 + 4]);
                af[mt][3] = tf32b(As[(r + 8) * 20 + kb + t4 + 4]);
            }
#pragma unroll
            for (int nt = 0; nt < 8; nt++) {
                int n = wn * 64 + nt * 8 + grp;
                bf[nt][0] = tf32b(Bs[(kb + t4) * 136 + n]);
                bf[nt][1] = tf32b(Bs[(kb + t4 + 4) * 136 + n]);
            }
#pragma unroll
            for (int mt = 0; mt < 2; mt++)
#pragma unroll
                for (int nt = 0; nt < 8; nt++)
                    mma8(acc[mt][nt], af[mt], bf[nt]);
        }
    }

    // Epilogue: bias add, float2 stores
#pragma unroll
    for (int mt = 0; mt < 2; mt++) {
        int r0 = m0 + wm * 32 + mt * 16 + grp;
#pragma unroll
        for (int nt = 0; nt < 8; nt++) {
            int col = n0 + wn * 64 + nt * 8 + t4 * 2;
            float b0v = bias[col], b1v = bias[col + 1];
            *(float2*)(C + (size_t)r0 * DM + col) =
                make_float2(acc[mt][nt][0] + b0v, acc[mt][nt][1] + b1v);
            *(float2*)(C + (size_t)(r0 + 8) * DM + col) =
                make_float2(acc[mt][nt][2] + b0v, acc[mt][nt][3] + b1v);
        }
    }
}

// ---------------------------------------------------------------------------
// Flash attention v2, TF32 MMA. Per CTA: (b, h, 128-query tile), 8 warps.
// Each warp owns 16 query rows x ALL 64 keys of the key tile -> softmax is
// fully warp-local (quad shuffles only), P is warp-private in smem
// (__syncwarp between P-store and PV). Two __syncthreads per key tile.
// Pitches Q/K/P:68, V:72 -> conflict-free fragment LDS.
// ---------------------------------------------------------------------------
#define QP2 68
#define KP2 68
#define VP2 72
#define PP2 68
#define FLASH_SMEM ((128 * QP2 + 64 * KP2 + 64 * VP2 + 128 * PP2 + 64) * 4)

__global__ __launch_bounds__(256, 2) void flash_tf32_kernel(
    const float* __restrict__ Q, const float* __restrict__ K,
    const float* __restrict__ V, const int* __restrict__ mask,
    float* __restrict__ O)
{
    extern __shared__ float sm[];
    float* Qs = sm;                   // [128][QP2]
    float* Ks = Qs + 128 * QP2;       // [64][KP2]   (row = key seq pos)
    float* Vs = Ks + 64 * KP2;        // [64][VP2]   (row = key seq pos, col = d)
    float* Ps = Vs + 64 * VP2;        // [128][PP2]  (warp-private 16-row bands)
    int*   mskp = (int*)(Ps + 128 * PP2); // [64]

    const int b  = blockIdx.z;
    const int h  = blockIdx.y;
    const int q0 = blockIdx.x * 128;
    const int tid  = threadIdx.x;
    const int lane = tid & 31;
    const int w    = tid >> 5;
    const int grp  = lane >> 2;
    const int t4   = lane & 3;
    const int qrow = w * 16 + grp;    // tile row of this thread's first row

    // Load Q tile 128x64 (tf32-rounded)
    const float* Qg = Q + ((size_t)(b * SEQ + q0) * DM + h * DH);
#pragma unroll
    for (int t = 0; t < 8; t++) {
        int f = tid + t * 256;
        int r = f >> 4, c = (f & 15) * 4;
        *(float4*)&Qs[r * QP2 + c] = tf32r4(*(const float4*)(Qg + (size_t)r * DM + c));
    }

    float o[8][4];
#pragma unroll
    for (int nt = 0; nt < 8; nt++)
#pragma unroll
        for (int c = 0; c < 4; c++) o[nt][c] = 0.f;
    float m0r = -INFINITY, m1r = -INFINITY, l0 = 0.f, l1 = 0.f;

    for (int kt = 0; kt < SEQ / 64; kt++) {
        __syncthreads();   // prior PV reads of Ks/Vs done before overwrite
        const float* Kg = K + ((size_t)(b * SEQ + kt * 64) * DM + h * DH);
        const float* Vg = V + ((size_t)(b * SEQ + kt * 64) * DM + h * DH);
#pragma unroll
        for (int t = 0; t < 4; t++) {
            int f = tid + t * 256;
            int r = f >> 4, c = (f & 15) * 4;
            *(float4*)&Ks[r * KP2 + c] = tf32r4(*(const float4*)(Kg + (size_t)r * DM + c));
            *(float4*)&Vs[r * VP2 + c] = tf32r4(*(const float4*)(Vg + (size_t)r * DM + c));
        }
        if (tid < 64) mskp[tid] = mask[b * SEQ + kt * 64 + tid];
        __syncthreads();  // also covers the initial Q fill on kt==0

        // ---- S = Q K^T : warp computes S[16q x 64k] ----
        float s[8][4];
#pragma unroll
        for (int nt = 0; nt < 8; nt++)
#pragma unroll
            for (int c = 0; c < 4; c++) s[nt][c] = 0.f;

#pragma unroll
        for (int k8 = 0; k8 < 8; k8++) {
            const int kb = k8 * 8;
            uint32_t af[4];
            af[0] = fbits(Qs[qrow * QP2 + kb + t4]);
            af[1] = fbits(Qs[(qrow + 8) * QP2 + kb + t4]);
            af[2] = fbits(Qs[qrow * QP2 + kb + t4 + 4]);
            af[3] = fbits(Qs[(qrow + 8) * QP2 + kb + t4 + 4]);
#pragma unroll
            for (int nt = 0; nt < 8; nt++) {
                int key = nt * 8 + grp;
                uint32_t bf[2] = { fbits(Ks[key * KP2 + kb + t4]),
                                   fbits(Ks[key * KP2 + kb + t4 + 4]) };
                mma8(s[nt], af, bf);
            }
        }

        // ---- scale + key-padding mask + warp-local row max ----
        float mx0 = -INFINITY, mx1 = -INFINITY;
#pragma unroll
        for (int nt = 0; nt < 8; nt++) {
            int key = nt * 8 + t4 * 2;
            int mk0 = mskp[key], mk1 = mskp[key + 1];
            s[nt][0] = mk0 ? -1e30f : s[nt][0] * SCALE_F;
            s[nt][1] = mk1 ? -1e30f : s[nt][1] * SCALE_F;
            s[nt][2] = mk0 ? -1e30f : s[nt][2] * SCALE_F;
            s[nt][3] = mk1 ? -1e30f : s[nt][3] * SCALE_F;
            mx0 = fmaxf(mx0, fmaxf(s[nt][0], s[nt][1]));
            mx1 = fmaxf(mx1, fmaxf(s[nt][2], s[nt][3]));
        }
        mx0 = fmaxf(mx0, __shfl_xor_sync(0xffffffffu, mx0, 1));
        mx0 = fmaxf(mx0, __shfl_xor_sync(0xffffffffu, mx0, 2));
        mx1 = fmaxf(mx1, __shfl_xor_sync(0xffffffffu, mx1, 1));
        mx1 = fmaxf(mx1, __shfl_xor_sync(0xffffffffu, mx1, 2));
        float mn0 = fmaxf(m0r, mx0);
        float mn1 = fmaxf(m1r, mx1);

        // ---- p = exp(s - mnew); store tf32-rounded to warp-private Ps ----
        float ls0 = 0.f, ls1 = 0.f;
#pragma unroll
        for (int nt = 0; nt < 8; nt++) {
            float p0 = __expf(s[nt][0] - mn0), p1 = __expf(s[nt][1] - mn0);
            float p2 = __expf(s[nt][2] - mn1), p3 = __expf(s[nt][3] - mn1);
            ls0 += p0 + p1; ls1 += p2 + p3;
            int key = nt * 8 + t4 * 2;
            *(float2*)&Ps[qrow * PP2 + key]       = make_float2(tf32r(p0), tf32r(p1));
            *(float2*)&Ps[(qrow + 8) * PP2 + key] = make_float2(tf32r(p2), tf32r(p3));
        }
        ls0 += __shfl_xor_sync(0xffffffffu, ls0, 1);
        ls0 += __shfl_xor_sync(0xffffffffu, ls0, 2);
        ls1 += __shfl_xor_sync(0xffffffffu, ls1, 1);
        ls1 += __shfl_xor_sync(0xffffffffu, ls1, 2);

        float a0 = __expf(m0r - mn0), a1 = __expf(m1r - mn1);
        l0 = l0 * a0 + ls0;
        l1 = l1 * a1 + ls1;
        m0r = mn0; m1r = mn1;
#pragma unroll
        for (int nt = 0; nt < 8; nt++) {
            o[nt][0] *= a0; o[nt][1] *= a0; o[nt][2] *= a1; o[nt][3] *= a1;
        }
        __syncwarp();   // Ps band written by this warp, visible to this warp

        // ---- O += P V : warp computes O[16q x 64d] ----
#pragma unroll
        for (int k8 = 0; k8 < 8; k8++) {
            const int kb = k8 * 8;
            uint32_t af[4];
            af[0] = fbits(Ps[qrow * PP2 + kb + t4]);
            af[1] = fbits(Ps[(qrow + 8) * PP2 + kb + t4]);
            af[2] = fbits(Ps[qrow * PP2 + kb + t4 + 4]);
            af[3] = fbits(Ps[(qrow + 8) * PP2 + kb + t4 + 4]);
#pragma unroll
            for (int nt = 0; nt < 8; nt++) {
                int d = nt * 8 + grp;
                uint32_t bf[2] = { fbits(Vs[(kb + t4) * VP2 + d]),
                                   fbits(Vs[(kb + t4 + 4) * VP2 + d]) };
                mma8(o[nt], af, bf);
            }
        }
    }

    // ---- epilogue: normalize, store [b, q, h*64 + d] ----
    float inv0 = 1.f / l0, inv1 = 1.f / l1;
#pragma unroll
    for (int nt = 0; nt < 8; nt++) {
        int d = nt * 8 + t4 * 2;
        float* Og = O + ((size_t)(b * SEQ + q0 + qrow) * DM + h * DH + d);
        *(float2*)Og = make_float2(o[nt][0] * inv0, o[nt][1] * inv0);
        *(float2*)(Og + (size_t)8 * DM) = make_float2(o[nt][2] * inv1, o[nt][3] * inv1);
    }
}

// ---------------------------------------------------------------------------
// kernel_launch: QKV projections -> flash attention -> output projection
// ---------------------------------------------------------------------------
extern "C" void kernel_launch(void* const* d_in, const int* in_sizes, int n_in,
                              void* d_out, int out_size)
{
    const float* x    = (const float*)d_in[0];
    const int*   mask = (const int*)  d_in[1];
    const float* Wq   = (const float*)d_in[2];
    const float* bq   = (const float*)d_in[3];
    const float* Wk   = (const float*)d_in[4];
    const float* bk   = (const float*)d_in[5];
    const float* Wv   = (const float*)d_in[6];
    const float* bv   = (const float*)d_in[7];
    const float* Wf   = (const float*)d_in[8];
    const float* bf   = (const float*)d_in[9];
    float* out = (float*)d_out;

    static float *q = nullptr, *k = nullptr, *v = nullptr, *att = nullptr;
    static int init_done = 0;
    if (!init_done) {
        cudaGetSymbolAddress((void**)&q,   g_q);
        cudaGetSymbolAddress((void**)&k,   g_k);
        cudaGetSymbolAddress((void**)&v,   g_v);
        cudaGetSymbolAddress((void**)&att, g_att);
        cudaFuncSetAttribute(gemm_tf32_kernel,
                             cudaFuncAttributeMaxDynamicSharedMemorySize, GEMM_SMEM);
        cudaFuncSetAttribute(flash_tf32_kernel,
                             cudaFuncAttributeMaxDynamicSharedMemorySize, FLASH_SMEM);
        init_done = 1;
    }

    dim3 blk(256);

    // 1) fused Q/K/V projections (TF32 MMA, cp.async pipeline)
    dim3 g1(DM / 128, NROWS / 128, 3);
    gemm_tf32_kernel<<<g1, blk, GEMM_SMEM>>>(x, Wq, Wk, Wv, bq, bk, bv, q, k, v);

    // 2) flash attention (TF32 MMA, warp-autonomous softmax)
    dim3 g2(SEQ / 128, NH, BSZ);
    flash_tf32_kernel<<<g2, blk, FLASH_SMEM>>>(q, k, v, mask, att);

    // 3) output projection
    dim3 g3(DM / 128, NROWS / 128, 1);
    gemm_tf32_kernel<<<g3, blk, GEMM_SMEM>>>(att, Wf, Wf, Wf, bf, bf, bf, out, out, out);
}